// round 1
// baseline (speedup 1.0000x reference)
#include <cuda_runtime.h>
#include <cuda_bf16.h>
#include <math.h>
#include <float.h>
#include <stdint.h>

// Problem constants
#define BATCH 16
#define PAIRS 8
#define NPTS  2048
#define DIM   256

// GEMM tiling
#define BM 128
#define BN 128
#define BK 32
#define SPAD 36   // smem row stride (floats) -> conflict-free frag loads

// ---------------- device scratch ----------------
__device__ float  g_mdesc[(size_t)BATCH * NPTS * DIM];            // 33.5 MB
__device__ float  g_S[(size_t)PAIRS * NPTS * NPTS];               // 134 MB
__device__ float  g_lsP[BATCH * NPTS];                            // logsigmoid(m)
__device__ float  g_lsN[BATCH * NPTS];                            // logsigmoid(-m)
__device__ float2 g_rstat[PAIRS * NPTS];                          // row (max, log sumexp)
__device__ float2 g_cpart[4 * PAIRS * NPTS];                      // col partials
__device__ float2 g_cstat[PAIRS * NPTS];                          // col (max, log sumexp)

// ---------------- helpers ----------------
__device__ __forceinline__ unsigned f2tf(float x) {
    unsigned r;
    asm("cvt.rna.tf32.f32 %0, %1;" : "=r"(r) : "f"(x));
    return r;
}

__device__ __forceinline__ void mma_tf32(float c[4], const unsigned a[4], const unsigned b[2]) {
    asm volatile(
        "mma.sync.aligned.m16n8k8.row.col.f32.tf32.tf32.f32 "
        "{%0,%1,%2,%3},{%4,%5,%6,%7},{%8,%9},{%0,%1,%2,%3};"
        : "+f"(c[0]), "+f"(c[1]), "+f"(c[2]), "+f"(c[3])
        : "r"(a[0]), "r"(a[1]), "r"(a[2]), "r"(a[3]), "r"(b[0]), "r"(b[1]));
}

__device__ __forceinline__ float logsigmoidf(float x) {
    // -log(1+exp(-x)) computed stably
    return fminf(x, 0.f) - log1pf(expf(-fabsf(x)));
}

__device__ __forceinline__ float warpMax(float v) {
    #pragma unroll
    for (int o = 16; o > 0; o >>= 1) v = fmaxf(v, __shfl_xor_sync(0xffffffffu, v, o));
    return v;
}
__device__ __forceinline__ float warpSum(float v) {
    #pragma unroll
    for (int o = 16; o > 0; o >>= 1) v += __shfl_xor_sync(0xffffffffu, v, o);
    return v;
}

// ---------------- K1: projection GEMM ----------------
// m_desc[row][col] = (sum_k desc[row][k] * W[col][k] + b[col]) * 0.25
__global__ __launch_bounds__(256) void proj_gemm(const float* __restrict__ A,
                                                 const float* __restrict__ W,
                                                 const float* __restrict__ bias) {
    __shared__ unsigned sA[BM][SPAD];
    __shared__ unsigned sB[BN][SPAD];

    const int tid = threadIdx.x;
    const int wid = tid >> 5, lane = tid & 31;
    const int wm = wid >> 2, wn = wid & 3;     // 2x4 warp grid, warp tile 64x32
    const int g = lane >> 2, t = lane & 3;

    const int rowBase = blockIdx.y * BM;
    const int colBase = blockIdx.x * BN;

    float acc[4][4][4];
    #pragma unroll
    for (int mi = 0; mi < 4; mi++)
        #pragma unroll
        for (int ni = 0; ni < 4; ni++)
            #pragma unroll
            for (int e = 0; e < 4; e++) acc[mi][ni][e] = 0.f;

    for (int kb = 0; kb < DIM; kb += BK) {
        #pragma unroll
        for (int i = 0; i < 4; i++) {
            int idx = tid + i * 256;
            int r = idx >> 3;
            int c = (idx & 7) * 4;
            float4 va = *(const float4*)(A + (size_t)(rowBase + r) * DIM + kb + c);
            sA[r][c+0] = f2tf(va.x); sA[r][c+1] = f2tf(va.y);
            sA[r][c+2] = f2tf(va.z); sA[r][c+3] = f2tf(va.w);
            float4 vb = *(const float4*)(W + (size_t)(colBase + r) * DIM + kb + c);
            sB[r][c+0] = f2tf(vb.x); sB[r][c+1] = f2tf(vb.y);
            sB[r][c+2] = f2tf(vb.z); sB[r][c+3] = f2tf(vb.w);
        }
        __syncthreads();

        #pragma unroll
        for (int ks = 0; ks < 4; ks++) {
            const int k0 = ks * 8;
            unsigned a[4][4], b[4][2];
            #pragma unroll
            for (int mi = 0; mi < 4; mi++) {
                int r0 = wm * 64 + mi * 16 + g;
                a[mi][0] = sA[r0][k0 + t];
                a[mi][1] = sA[r0 + 8][k0 + t];
                a[mi][2] = sA[r0][k0 + t + 4];
                a[mi][3] = sA[r0 + 8][k0 + t + 4];
            }
            #pragma unroll
            for (int ni = 0; ni < 4; ni++) {
                int c0 = wn * 32 + ni * 8 + g;
                b[ni][0] = sB[c0][k0 + t];
                b[ni][1] = sB[c0][k0 + t + 4];
            }
            #pragma unroll
            for (int mi = 0; mi < 4; mi++)
                #pragma unroll
                for (int ni = 0; ni < 4; ni++)
                    mma_tf32(acc[mi][ni], a[mi], b[ni]);
        }
        __syncthreads();
    }

    #pragma unroll
    for (int mi = 0; mi < 4; mi++) {
        #pragma unroll
        for (int ni = 0; ni < 4; ni++) {
            #pragma unroll
            for (int e = 0; e < 4; e++) {
                int row = rowBase + wm * 64 + mi * 16 + g + (e >> 1) * 8;
                int col = colBase + wn * 32 + ni * 8 + 2 * t + (e & 1);
                g_mdesc[(size_t)row * DIM + col] = (acc[mi][ni][e] + bias[col]) * 0.25f;
            }
        }
    }
}

// ---------------- K2: similarity GEMM with mask epilogue ----------------
__global__ __launch_bounds__(256) void sim_gemm(const int* __restrict__ mask) {
    __shared__ unsigned sA[BM][SPAD];
    __shared__ unsigned sB[BN][SPAD];

    const int tid = threadIdx.x;
    const int wid = tid >> 5, lane = tid & 31;
    const int wm = wid >> 2, wn = wid & 3;
    const int g = lane >> 2, t = lane & 3;

    const int p = blockIdx.z;
    const int rowBase = blockIdx.y * BM;
    const int colBase = blockIdx.x * BN;

    const float* Ap = g_mdesc + (size_t)(2 * p) * NPTS * DIM;
    const float* Bp = g_mdesc + (size_t)(2 * p + 1) * NPTS * DIM;

    float acc[4][4][4];
    #pragma unroll
    for (int mi = 0; mi < 4; mi++)
        #pragma unroll
        for (int ni = 0; ni < 4; ni++)
            #pragma unroll
            for (int e = 0; e < 4; e++) acc[mi][ni][e] = 0.f;

    for (int kb = 0; kb < DIM; kb += BK) {
        #pragma unroll
        for (int i = 0; i < 4; i++) {
            int idx = tid + i * 256;
            int r = idx >> 3;
            int c = (idx & 7) * 4;
            float4 va = *(const float4*)(Ap + (size_t)(rowBase + r) * DIM + kb + c);
            sA[r][c+0] = f2tf(va.x); sA[r][c+1] = f2tf(va.y);
            sA[r][c+2] = f2tf(va.z); sA[r][c+3] = f2tf(va.w);
            float4 vb = *(const float4*)(Bp + (size_t)(colBase + r) * DIM + kb + c);
            sB[r][c+0] = f2tf(vb.x); sB[r][c+1] = f2tf(vb.y);
            sB[r][c+2] = f2tf(vb.z); sB[r][c+3] = f2tf(vb.w);
        }
        __syncthreads();

        #pragma unroll
        for (int ks = 0; ks < 4; ks++) {
            const int k0 = ks * 8;
            unsigned a[4][4], b[4][2];
            #pragma unroll
            for (int mi = 0; mi < 4; mi++) {
                int r0 = wm * 64 + mi * 16 + g;
                a[mi][0] = sA[r0][k0 + t];
                a[mi][1] = sA[r0 + 8][k0 + t];
                a[mi][2] = sA[r0][k0 + t + 4];
                a[mi][3] = sA[r0 + 8][k0 + t + 4];
            }
            #pragma unroll
            for (int ni = 0; ni < 4; ni++) {
                int c0 = wn * 32 + ni * 8 + g;
                b[ni][0] = sB[c0][k0 + t];
                b[ni][1] = sB[c0][k0 + t + 4];
            }
            #pragma unroll
            for (int mi = 0; mi < 4; mi++)
                #pragma unroll
                for (int ni = 0; ni < 4; ni++)
                    mma_tf32(acc[mi][ni], a[mi], b[ni]);
        }
        __syncthreads();
    }

    // mask epilogue
    const int* m0 = mask + (size_t)(2 * p) * NPTS;
    const int* m1 = mask + (size_t)(2 * p + 1) * NPTS;
    int rmask[4][2], cmask[4];
    #pragma unroll
    for (int mi = 0; mi < 4; mi++) {
        rmask[mi][0] = m0[rowBase + wm * 64 + mi * 16 + g];
        rmask[mi][1] = m0[rowBase + wm * 64 + mi * 16 + g + 8];
    }
    #pragma unroll
    for (int ni = 0; ni < 4; ni++) {
        // columns for this thread: 2t and 2t+1 within n-tile ni
        cmask[ni] = 0;  // placeholder, handled per-element below
    }
    (void)cmask;
    float* Sp = g_S + (size_t)p * NPTS * NPTS;
    #pragma unroll
    for (int mi = 0; mi < 4; mi++) {
        #pragma unroll
        for (int ni = 0; ni < 4; ni++) {
            #pragma unroll
            for (int e = 0; e < 4; e++) {
                int row = rowBase + wm * 64 + mi * 16 + g + (e >> 1) * 8;
                int col = colBase + wn * 32 + ni * 8 + 2 * t + (e & 1);
                int mk = rmask[mi][e >> 1] * m1[col];
                float v = (mk != 0) ? acc[mi][ni][e] : -FLT_MAX;
                Sp[(size_t)row * NPTS + col] = v;
            }
        }
    }
}

// ---------------- K_match: matchability + logsigmoids ----------------
__global__ __launch_bounds__(256) void match_kernel(const float* __restrict__ desc,
                                                    const float* __restrict__ mw,
                                                    const float* __restrict__ mb) {
    int warp = blockIdx.x * 8 + (threadIdx.x >> 5);   // row 0..32767
    int lane = threadIdx.x & 31;
    const float* dp = desc + (size_t)warp * DIM;
    float acc = 0.f;
    #pragma unroll
    for (int i = 0; i < 8; i++)
        acc = fmaf(dp[lane + 32 * i], mw[lane + 32 * i], acc);
    acc = warpSum(acc);
    if (lane == 0) {
        float m = acc + mb[0];
        g_lsP[warp] = logsigmoidf(m);
        g_lsN[warp] = logsigmoidf(-m);
    }
}

// ---------------- K3: row logsumexp ----------------
__global__ __launch_bounds__(256) void row_lse() {
    const int row = blockIdx.x;                     // p*NPTS + n
    const float* sp = g_S + (size_t)row * NPTS;
    const int tid = threadIdx.x;
    const int wid = tid >> 5, lane = tid & 31;
    __shared__ float red[8];
    __shared__ float bcast;

    float v[8];
    #pragma unroll
    for (int i = 0; i < 8; i++) v[i] = sp[tid + i * 256];

    float mx = v[0];
    #pragma unroll
    for (int i = 1; i < 8; i++) mx = fmaxf(mx, v[i]);
    mx = warpMax(mx);
    if (lane == 0) red[wid] = mx;
    __syncthreads();
    if (tid == 0) {
        float b = red[0];
        #pragma unroll
        for (int i = 1; i < 8; i++) b = fmaxf(b, red[i]);
        bcast = b;
    }
    __syncthreads();
    float bmax = bcast;

    float s = 0.f;
    #pragma unroll
    for (int i = 0; i < 8; i++) s += expf(v[i] - bmax);
    s = warpSum(s);
    __syncthreads();
    if (lane == 0) red[wid] = s;
    __syncthreads();
    if (tid == 0) {
        float tot = 0.f;
        #pragma unroll
        for (int i = 0; i < 8; i++) tot += red[i];
        g_rstat[row] = make_float2(bmax, logf(tot));
    }
}

// ---------------- K4: column logsumexp (partials) ----------------
__global__ __launch_bounds__(256) void col_lse_part() {
    const int t = threadIdx.x;
    const int c = blockIdx.x * 64 + (t & 63);
    const int rs = blockIdx.y;                      // row split 0..3
    const int p = blockIdx.z;
    const float* base = g_S + (size_t)p * NPTS * NPTS + c;

    float m = -FLT_MAX, s = 0.f;
    for (int r = rs * 512 + (t >> 6); r < rs * 512 + 512; r += 4) {
        float x = base[(size_t)r * NPTS];
        if (x > m) { s = s * expf(m - x) + 1.f; m = x; }
        else       { s += expf(x - m); }
    }

    __shared__ float sm[256], ss[256];
    sm[t] = m; ss[t] = s;
    __syncthreads();
    if (t < 64) {
        float M = sm[t], S = ss[t];
        #pragma unroll
        for (int j = 1; j < 4; j++) {
            float m2 = sm[t + 64 * j], s2 = ss[t + 64 * j];
            float Mn = fmaxf(M, m2);
            S = S * expf(M - Mn) + s2 * expf(m2 - Mn);
            M = Mn;
        }
        g_cpart[((size_t)rs * PAIRS + p) * NPTS + c] = make_float2(M, S);
    }
}

__global__ __launch_bounds__(256) void col_lse_merge() {
    int idx = blockIdx.x * 256 + threadIdx.x;       // p*NPTS + c
    if (idx >= PAIRS * NPTS) return;
    int p = idx / NPTS, c = idx % NPTS;
    float2 a = g_cpart[((size_t)0 * PAIRS + p) * NPTS + c];
    float M = a.x, S = a.y;
    #pragma unroll
    for (int rs = 1; rs < 4; rs++) {
        float2 b = g_cpart[((size_t)rs * PAIRS + p) * NPTS + c];
        float Mn = fmaxf(M, b.x);
        S = S * expf(M - Mn) + b.y * expf(b.x - Mn);
        M = Mn;
    }
    g_cstat[idx] = make_float2(M, logf(S));
}

// ---------------- K5: final assembly ----------------
#define NOUT (NPTS + 1)
__global__ __launch_bounds__(256) void final_kernel(float* __restrict__ out) {
    const int m = blockIdx.x * 256 + threadIdx.x;
    const int n = blockIdx.y;
    const int p = blockIdx.z;
    if (m > NPTS) return;

    float* o = out + (((size_t)p * NOUT) + n) * NOUT + m;
    if (n < NPTS && m < NPTS) {
        float s = g_S[((size_t)p * NPTS + n) * NPTS + m];
        float2 r = g_rstat[p * NPTS + n];
        float2 c = g_cstat[p * NPTS + m];
        float sc0 = (s - r.x) - r.y;
        float sc1 = (s - c.x) - c.y;
        float cert = g_lsP[(2 * p) * NPTS + n] + g_lsP[(2 * p + 1) * NPTS + m];
        *o = (sc0 + sc1) + cert;
    } else if (n == NPTS && m < NPTS) {
        *o = g_lsN[(2 * p + 1) * NPTS + m];
    } else if (m == NPTS && n < NPTS) {
        *o = g_lsN[(2 * p) * NPTS + n];
    } else {
        *o = 0.f;
    }
}

// ---------------- launch ----------------
extern "C" void kernel_launch(void* const* d_in, const int* in_sizes, int n_in,
                              void* d_out, int out_size) {
    const float* descriptors = (const float*)d_in[0];
    const int*   mask        = (const int*)d_in[1];
    const float* proj_w      = (const float*)d_in[2];
    const float* proj_b      = (const float*)d_in[3];
    const float* match_w     = (const float*)d_in[4];
    const float* match_b     = (const float*)d_in[5];
    float* out = (float*)d_out;

    // K1: projection GEMM  (M=32768, N=256)
    proj_gemm<<<dim3(DIM / BN, (BATCH * NPTS) / BM, 1), 256>>>(descriptors, proj_w, proj_b);

    // matchability
    match_kernel<<<(BATCH * NPTS) / 8, 256>>>(descriptors, match_w, match_b);

    // K2: similarity GEMMs
    sim_gemm<<<dim3(NPTS / BN, NPTS / BM, PAIRS), 256>>>(mask);

    // K3: row logsumexp
    row_lse<<<PAIRS * NPTS, 256>>>();

    // K4: column logsumexp
    col_lse_part<<<dim3(NPTS / 64, 4, PAIRS), 256>>>();
    col_lse_merge<<<(PAIRS * NPTS + 255) / 256, 256>>>();

    // K5: final assembly
    final_kernel<<<dim3((NOUT + 255) / 256, NOUT, PAIRS), 256>>>(out);
}

// round 2
// speedup vs baseline: 1.4247x; 1.4247x over previous
#include <cuda_runtime.h>
#include <cuda_bf16.h>
#include <math.h>
#include <float.h>
#include <stdint.h>

// Problem constants
#define BATCH 16
#define PAIRS 8
#define NPTS  2048
#define DIM   256

// GEMM tiling
#define BM 128
#define BN 128
#define BKH 32          // bf16 elements per k-block
#define SW 20           // smem row stride in uint32 (16 data + 4 pad) -> conflict-free

// ---------------- device scratch ----------------
__device__ __nv_bfloat16 g_mdescH[(size_t)BATCH * NPTS * DIM];    // 16.8 MB
__device__ float  g_S[(size_t)PAIRS * NPTS * NPTS];               // 134 MB
__device__ float  g_lsP[BATCH * NPTS];                            // logsigmoid(m)
__device__ float  g_lsN[BATCH * NPTS];                            // logsigmoid(-m)
__device__ float2 g_rstat[PAIRS * NPTS];                          // row (max, log sumexp)
__device__ float2 g_cpart[64 * PAIRS * NPTS];                     // col partials per 32-row chunk
__device__ float2 g_cstat[PAIRS * NPTS];                          // col (max, log sumexp)

// ---------------- helpers ----------------
__device__ __forceinline__ unsigned pack_bf16(float lo, float hi) {
    unsigned r;
    asm("cvt.rn.bf16x2.f32 %0, %1, %2;" : "=r"(r) : "f"(hi), "f"(lo));
    return r;
}

__device__ __forceinline__ void mma_bf16(float c[4], const unsigned a[4], const unsigned b[2]) {
    asm volatile(
        "mma.sync.aligned.m16n8k16.row.col.f32.bf16.bf16.f32 "
        "{%0,%1,%2,%3},{%4,%5,%6,%7},{%8,%9},{%0,%1,%2,%3};"
        : "+f"(c[0]), "+f"(c[1]), "+f"(c[2]), "+f"(c[3])
        : "r"(a[0]), "r"(a[1]), "r"(a[2]), "r"(a[3]), "r"(b[0]), "r"(b[1]));
}

__device__ __forceinline__ float logsigmoidf(float x) {
    return fminf(x, 0.f) - log1pf(expf(-fabsf(x)));
}

__device__ __forceinline__ float warpSum(float v) {
    #pragma unroll
    for (int o = 16; o > 0; o >>= 1) v += __shfl_xor_sync(0xffffffffu, v, o);
    return v;
}

// online (max, sumexp) combine
__device__ __forceinline__ void lse_combine(float& M, float& S, float m2, float s2) {
    float Mn = fmaxf(M, m2);
    S = S * __expf(M - Mn) + s2 * __expf(m2 - Mn);
    M = Mn;
}

// ---------------- K1: projection GEMM (fp32 in -> bf16 mma -> bf16 out) ----------------
__global__ __launch_bounds__(256) void proj_gemm(const float* __restrict__ A,
                                                 const float* __restrict__ W,
                                                 const float* __restrict__ bias) {
    __shared__ unsigned sA[BM][SW];
    __shared__ unsigned sB[BN][SW];

    const int tid = threadIdx.x;
    const int wid = tid >> 5, lane = tid & 31;
    const int wm = wid >> 2, wn = wid & 3;     // 2x4 warp grid, warp tile 64x32
    const int g = lane >> 2, t = lane & 3;

    const int rowBase = blockIdx.y * BM;
    const int colBase = blockIdx.x * BN;

    float acc[4][4][4];
    #pragma unroll
    for (int mi = 0; mi < 4; mi++)
        #pragma unroll
        for (int ni = 0; ni < 4; ni++)
            #pragma unroll
            for (int e = 0; e < 4; e++) acc[mi][ni][e] = 0.f;

    for (int kb = 0; kb < DIM; kb += BKH) {
        #pragma unroll
        for (int i = 0; i < 4; i++) {
            int idx = tid + i * 256;           // 0..1023
            int r = idx >> 3;
            int c4 = idx & 7;                  // float4 col (4 floats = 2 uint32 pairs)
            float4 va = *(const float4*)(A + (size_t)(rowBase + r) * DIM + kb + c4 * 4);
            sA[r][c4 * 2 + 0] = pack_bf16(va.x, va.y);
            sA[r][c4 * 2 + 1] = pack_bf16(va.z, va.w);
            float4 vb = *(const float4*)(W + (size_t)(colBase + r) * DIM + kb + c4 * 4);
            sB[r][c4 * 2 + 0] = pack_bf16(vb.x, vb.y);
            sB[r][c4 * 2 + 1] = pack_bf16(vb.z, vb.w);
        }
        __syncthreads();

        #pragma unroll
        for (int ks = 0; ks < 2; ks++) {
            const int j0 = ks * 8;             // uint32 col base (8 pairs = 16 bf16)
            unsigned a[4][4], b[4][2];
            #pragma unroll
            for (int mi = 0; mi < 4; mi++) {
                int r0 = wm * 64 + mi * 16 + g;
                a[mi][0] = sA[r0][j0 + t];
                a[mi][1] = sA[r0 + 8][j0 + t];
                a[mi][2] = sA[r0][j0 + t + 4];
                a[mi][3] = sA[r0 + 8][j0 + t + 4];
            }
            #pragma unroll
            for (int ni = 0; ni < 4; ni++) {
                int c0 = wn * 32 + ni * 8 + g;
                b[ni][0] = sB[c0][j0 + t];
                b[ni][1] = sB[c0][j0 + t + 4];
            }
            #pragma unroll
            for (int mi = 0; mi < 4; mi++)
                #pragma unroll
                for (int ni = 0; ni < 4; ni++)
                    mma_bf16(acc[mi][ni], a[mi], b[ni]);
        }
        __syncthreads();
    }

    #pragma unroll
    for (int mi = 0; mi < 4; mi++) {
        #pragma unroll
        for (int ni = 0; ni < 4; ni++) {
            #pragma unroll
            for (int eh = 0; eh < 2; eh++) {
                int row = rowBase + wm * 64 + mi * 16 + g + eh * 8;
                int col = colBase + wn * 32 + ni * 8 + 2 * t;
                float v0 = (acc[mi][ni][eh * 2 + 0] + bias[col])     * 0.25f;
                float v1 = (acc[mi][ni][eh * 2 + 1] + bias[col + 1]) * 0.25f;
                *(unsigned*)&g_mdescH[(size_t)row * DIM + col] = pack_bf16(v0, v1);
            }
        }
    }
}

// ---------------- K2: similarity GEMM (bf16, double-buffered) + mask epilogue ----------------
__global__ __launch_bounds__(256) void sim_gemm(const int* __restrict__ mask) {
    __shared__ unsigned sA[2][BM][SW];
    __shared__ unsigned sB[2][BN][SW];

    const int tid = threadIdx.x;
    const int wid = tid >> 5, lane = tid & 31;
    const int wm = wid >> 2, wn = wid & 3;
    const int g = lane >> 2, t = lane & 3;

    const int p = blockIdx.z;
    const int rowBase = blockIdx.y * BM;
    const int colBase = blockIdx.x * BN;

    const __nv_bfloat16* Ap = g_mdescH + (size_t)(2 * p) * NPTS * DIM;
    const __nv_bfloat16* Bp = g_mdescH + (size_t)(2 * p + 1) * NPTS * DIM;

    float acc[4][4][4];
    #pragma unroll
    for (int mi = 0; mi < 4; mi++)
        #pragma unroll
        for (int ni = 0; ni < 4; ni++)
            #pragma unroll
            for (int e = 0; e < 4; e++) acc[mi][ni][e] = 0.f;

    // per-thread global load coords (512 uint4 per tile / 256 threads = 2 each)
    const int r_ld[2]  = { tid >> 2, (tid + 256) >> 2 };
    const int c4_ld[2] = { tid & 3,  (tid + 256) & 3 };

    uint4 pa[2], pb[2];
    // prologue: load kb=0
    #pragma unroll
    for (int i = 0; i < 2; i++) {
        pa[i] = *(const uint4*)(Ap + (size_t)(rowBase + r_ld[i]) * DIM + c4_ld[i] * 8);
        pb[i] = *(const uint4*)(Bp + (size_t)(colBase + r_ld[i]) * DIM + c4_ld[i] * 8);
    }
    #pragma unroll
    for (int i = 0; i < 2; i++) {
        *(uint4*)&sA[0][r_ld[i]][c4_ld[i] * 4] = pa[i];
        *(uint4*)&sB[0][r_ld[i]][c4_ld[i] * 4] = pb[i];
    }
    __syncthreads();

    const int NKB = DIM / BKH;  // 8
    for (int kb = 0; kb < NKB; kb++) {
        const int cur = kb & 1;
        if (kb + 1 < NKB) {
            #pragma unroll
            for (int i = 0; i < 2; i++) {
                pa[i] = *(const uint4*)(Ap + (size_t)(rowBase + r_ld[i]) * DIM + (kb + 1) * BKH + c4_ld[i] * 8);
                pb[i] = *(const uint4*)(Bp + (size_t)(colBase + r_ld[i]) * DIM + (kb + 1) * BKH + c4_ld[i] * 8);
            }
        }

        #pragma unroll
        for (int ks = 0; ks < 2; ks++) {
            const int j0 = ks * 8;
            unsigned a[4][4], b[4][2];
            #pragma unroll
            for (int mi = 0; mi < 4; mi++) {
                int r0 = wm * 64 + mi * 16 + g;
                a[mi][0] = sA[cur][r0][j0 + t];
                a[mi][1] = sA[cur][r0 + 8][j0 + t];
                a[mi][2] = sA[cur][r0][j0 + t + 4];
                a[mi][3] = sA[cur][r0 + 8][j0 + t + 4];
            }
            #pragma unroll
            for (int ni = 0; ni < 4; ni++) {
                int c0 = wn * 32 + ni * 8 + g;
                b[ni][0] = sB[cur][c0][j0 + t];
                b[ni][1] = sB[cur][c0][j0 + t + 4];
            }
            #pragma unroll
            for (int mi = 0; mi < 4; mi++)
                #pragma unroll
                for (int ni = 0; ni < 4; ni++)
                    mma_bf16(acc[mi][ni], a[mi], b[ni]);
        }

        if (kb + 1 < NKB) {
            const int nxt = (kb + 1) & 1;
            #pragma unroll
            for (int i = 0; i < 2; i++) {
                *(uint4*)&sA[nxt][r_ld[i]][c4_ld[i] * 4] = pa[i];
                *(uint4*)&sB[nxt][r_ld[i]][c4_ld[i] * 4] = pb[i];
            }
            __syncthreads();
        }
    }

    // mask epilogue; masked entries are EXACTLY -FLT_MAX (preserves inf pattern)
    const int* m0 = mask + (size_t)(2 * p) * NPTS;
    const int* m1 = mask + (size_t)(2 * p + 1) * NPTS;
    float* Sp = g_S + (size_t)p * NPTS * NPTS;

    #pragma unroll
    for (int mi = 0; mi < 4; mi++) {
        int rm[2];
        rm[0] = m0[rowBase + wm * 64 + mi * 16 + g];
        rm[1] = m0[rowBase + wm * 64 + mi * 16 + g + 8];
        #pragma unroll
        for (int ni = 0; ni < 4; ni++) {
            int col = colBase + wn * 32 + ni * 8 + 2 * t;
            int cm0 = m1[col], cm1 = m1[col + 1];
            #pragma unroll
            for (int eh = 0; eh < 2; eh++) {
                int row = rowBase + wm * 64 + mi * 16 + g + eh * 8;
                float2 v;
                v.x = (rm[eh] && cm0) ? acc[mi][ni][eh * 2 + 0] : -FLT_MAX;
                v.y = (rm[eh] && cm1) ? acc[mi][ni][eh * 2 + 1] : -FLT_MAX;
                *(float2*)&Sp[(size_t)row * NPTS + col] = v;
            }
        }
    }
}

// ---------------- K_match: matchability + logsigmoids ----------------
__global__ __launch_bounds__(256) void match_kernel(const float* __restrict__ desc,
                                                    const float* __restrict__ mw,
                                                    const float* __restrict__ mb) {
    int warp = blockIdx.x * 8 + (threadIdx.x >> 5);
    int lane = threadIdx.x & 31;
    const float* dp = desc + (size_t)warp * DIM;
    float acc = 0.f;
    #pragma unroll
    for (int i = 0; i < 8; i++)
        acc = fmaf(dp[lane + 32 * i], mw[lane + 32 * i], acc);
    acc = warpSum(acc);
    if (lane == 0) {
        float m = acc + mb[0];
        g_lsP[warp] = logsigmoidf(m);
        g_lsN[warp] = logsigmoidf(-m);
    }
}

// ---------------- K3: fused row+col stats (one pass over S) ----------------
// Block: 32 full rows of one pair. Emits final row stats + column partials.
__global__ __launch_bounds__(256) void stats_kernel() {
    const int p = blockIdx.y;
    const int r0 = blockIdx.x * 32;
    const int tid = threadIdx.x;
    const int wrp = tid >> 5, lane = tid & 31;

    __shared__ float2 wpart[32][8];

    float colM[8], colS[8];
    #pragma unroll
    for (int i = 0; i < 8; i++) { colM[i] = -FLT_MAX; colS[i] = 0.f; }

    for (int r = 0; r < 32; r++) {
        const float* row = g_S + ((size_t)p * NPTS + r0 + r) * NPTS;
        float v[8];
        #pragma unroll
        for (int i = 0; i < 8; i++) v[i] = row[tid + 256 * i];

        // row partial (this thread's 8 cols)
        float m = v[0];
        #pragma unroll
        for (int i = 1; i < 8; i++) m = fmaxf(m, v[i]);
        float s = 0.f;
        #pragma unroll
        for (int i = 0; i < 8; i++) s += __expf(v[i] - m);
        // warp combine
        #pragma unroll
        for (int o = 16; o > 0; o >>= 1) {
            float om = __shfl_xor_sync(0xffffffffu, m, o);
            float os = __shfl_xor_sync(0xffffffffu, s, o);
            lse_combine(m, s, om, os);
        }
        if (lane == 0) wpart[r][wrp] = make_float2(m, s);

        // col accumulate
        #pragma unroll
        for (int i = 0; i < 8; i++) {
            float x = v[i];
            if (x > colM[i]) { colS[i] = colS[i] * __expf(colM[i] - x) + 1.f; colM[i] = x; }
            else             { colS[i] += __expf(x - colM[i]); }
        }
    }
    __syncthreads();

    if (tid < 32) {
        float2 a = wpart[tid][0];
        float M = a.x, S = a.y;
        #pragma unroll
        for (int w = 1; w < 8; w++) lse_combine(M, S, wpart[tid][w].x, wpart[tid][w].y);
        g_rstat[p * NPTS + r0 + tid] = make_float2(M, __logf(S));
    }

    // write col partials for this 32-row chunk
    #pragma unroll
    for (int i = 0; i < 8; i++) {
        int c = tid + 256 * i;
        g_cpart[((size_t)blockIdx.x * PAIRS + p) * NPTS + c] = make_float2(colM[i], colS[i]);
    }
}

__global__ __launch_bounds__(256) void col_lse_merge() {
    int idx = blockIdx.x * 256 + threadIdx.x;       // p*NPTS + c
    if (idx >= PAIRS * NPTS) return;
    float2 a = g_cpart[idx];
    float M = a.x, S = a.y;
    for (int ch = 1; ch < 64; ch++) {
        float2 b = g_cpart[(size_t)ch * PAIRS * NPTS + idx];
        lse_combine(M, S, b.x, b.y);
    }
    g_cstat[idx] = make_float2(M, __logf(S));
}

// ---------------- K5: final assembly ----------------
#define NOUT (NPTS + 1)
__global__ __launch_bounds__(256) void final_kernel(float* __restrict__ out) {
    const int m = blockIdx.x * 256 + threadIdx.x;
    const int n = blockIdx.y;
    const int p = blockIdx.z;
    if (m > NPTS) return;

    float* o = out + (((size_t)p * NOUT) + n) * NOUT + m;
    if (n < NPTS && m < NPTS) {
        float s = g_S[((size_t)p * NPTS + n) * NPTS + m];
        float2 r = g_rstat[p * NPTS + n];
        float2 c = g_cstat[p * NPTS + m];
        float sc0 = (s - r.x) - r.y;
        float sc1 = (s - c.x) - c.y;
        float cert = g_lsP[(2 * p) * NPTS + n] + g_lsP[(2 * p + 1) * NPTS + m];
        *o = (sc0 + sc1) + cert;
    } else if (n == NPTS && m < NPTS) {
        *o = g_lsN[(2 * p + 1) * NPTS + m];
    } else if (m == NPTS && n < NPTS) {
        *o = g_lsN[(2 * p) * NPTS + n];
    } else {
        *o = 0.f;
    }
}

// ---------------- launch ----------------
extern "C" void kernel_launch(void* const* d_in, const int* in_sizes, int n_in,
                              void* d_out, int out_size) {
    const float* descriptors = (const float*)d_in[0];
    const int*   mask        = (const int*)d_in[1];
    const float* proj_w      = (const float*)d_in[2];
    const float* proj_b      = (const float*)d_in[3];
    const float* match_w     = (const float*)d_in[4];
    const float* match_b     = (const float*)d_in[5];
    float* out = (float*)d_out;

    proj_gemm<<<dim3(DIM / BN, (BATCH * NPTS) / BM, 1), 256>>>(descriptors, proj_w, proj_b);
    match_kernel<<<(BATCH * NPTS) / 8, 256>>>(descriptors, match_w, match_b);
    sim_gemm<<<dim3(NPTS / BN, NPTS / BM, PAIRS), 256>>>(mask);
    stats_kernel<<<dim3(NPTS / 32, PAIRS), 256>>>();
    col_lse_merge<<<(PAIRS * NPTS + 255) / 256, 256>>>();
    final_kernel<<<dim3((NOUT + 255) / 256, NOUT, PAIRS), 256>>>(out);
}